// round 10
// baseline (speedup 1.0000x reference)
#include <cuda_runtime.h>
#include <math.h>

#define BB   64
#define NN   4096
#define DD   1024
#define DIN  2048
#define DHID 4096
#define NOUT 1000

typedef unsigned long long ull;

// ---- scratch (device globals; no allocation allowed) ----
__device__ float g_xn[BB * DD];        // normalized encoder
__device__ float g_z[BB * NN];         // sparsemax input scores
__device__ int   g_nzidx[BB * NN];     // compacted support indices
__device__ float g_nzw[BB * NN];       // compacted weights
__device__ int   g_nnz[BB];
__device__ float g_memvec[BB * DD];    // weighted memory readout (atomic acc)
__device__ float g_h1[BB * DHID];      // hidden pre-activations (bias + atomic acc)

// ---------------------------------------------------------------------------
// PRE: blocks [0,64):    xn = enc / max(||enc||,1e-6)
//      blocks [64,1088):  h1 = b1 (bcast)
//      blocks [1088,1344): memvec = 0
//      blocks [1344,1594): out = b2 (bcast)
//      1594 blocks x 256 — launch #1
// ---------------------------------------------------------------------------
__global__ void pre_all(const float* __restrict__ enc,
                        const float* __restrict__ b1,
                        const float* __restrict__ b2,
                        float* __restrict__ out) {
    int bid = blockIdx.x;
    if (bid < 64) {
        int b = bid;
        __shared__ float red[256];
        float ssq = 0.f;
        for (int i = threadIdx.x; i < DD; i += 256) {
            float v = enc[b * DD + i];
            ssq = fmaf(v, v, ssq);
        }
        red[threadIdx.x] = ssq;
        __syncthreads();
        for (int s = 128; s > 0; s >>= 1) {
            if (threadIdx.x < s) red[threadIdx.x] += red[threadIdx.x + s];
            __syncthreads();
        }
        float inv = 1.f / fmaxf(sqrtf(red[0]), 1e-6f);
        for (int i = threadIdx.x; i < DD; i += 256)
            g_xn[b * DD + i] = enc[b * DD + i] * inv;
    } else if (bid < 1088) {
        int i = (bid - 64) * 256 + threadIdx.x;        // BB*DHID
        g_h1[i] = b1[i & (DHID - 1)];
    } else if (bid < 1344) {
        int i = (bid - 1088) * 256 + threadIdx.x;      // BB*DD
        g_memvec[i] = 0.f;
    } else {
        int i = (bid - 1344) * 256 + threadIdx.x;      // BB*NOUT
        if (i < BB * NOUT) out[i] = b2[i % NOUT];
    }
}

// ---------------------------------------------------------------------------
// K1: the 1.07 GB pass (AT DRAM ROOFLINE, 6.63 TB/s — do not touch).
//     Launch #2. Zero smem, MLP=16 per row-pair.
// ---------------------------------------------------------------------------
__global__ void __launch_bounds__(256) k1_scores(const float* __restrict__ mem) {
    int warp = threadIdx.x >> 5, lane = threadIdx.x & 31;
    int rbase = blockIdx.x * 64 + warp * 8;
    int b = rbase >> 12;

    const float4* x4 = (const float4*)g_xn + (size_t)b * (DD / 4);
    float4 x[8];
#pragma unroll
    for (int i = 0; i < 8; i++) x[i] = x4[lane + i * 32];

    const float4* mrow = (const float4*)mem + (size_t)rbase * (DD / 4);

#pragma unroll
    for (int rr = 0; rr < 8; rr += 2) {
        const float4* A = mrow + rr * (DD / 4);
        const float4* C = A + (DD / 4);
        float4 a[8], c[8];
#pragma unroll
        for (int i = 0; i < 8; i++) {
            a[i] = __ldcs(&A[lane + i * 32]);
            c[i] = __ldcs(&C[lane + i * 32]);
        }
        float d0 = 0.f, s0 = 0.f, d1 = 0.f, s1 = 0.f;
#pragma unroll
        for (int i = 0; i < 8; i++) {
            float4 xv = x[i];
            d0 = fmaf(a[i].x, xv.x, fmaf(a[i].y, xv.y, fmaf(a[i].z, xv.z, fmaf(a[i].w, xv.w, d0))));
            s0 = fmaf(a[i].x, a[i].x, fmaf(a[i].y, a[i].y, fmaf(a[i].z, a[i].z, fmaf(a[i].w, a[i].w, s0))));
            d1 = fmaf(c[i].x, xv.x, fmaf(c[i].y, xv.y, fmaf(c[i].z, xv.z, fmaf(c[i].w, xv.w, d1))));
            s1 = fmaf(c[i].x, c[i].x, fmaf(c[i].y, c[i].y, fmaf(c[i].z, c[i].z, fmaf(c[i].w, c[i].w, s1))));
        }
#pragma unroll
        for (int o = 16; o; o >>= 1) {
            d0 += __shfl_xor_sync(0xFFFFFFFFu, d0, o);
            s0 += __shfl_xor_sync(0xFFFFFFFFu, s0, o);
            d1 += __shfl_xor_sync(0xFFFFFFFFu, d1, o);
            s1 += __shfl_xor_sync(0xFFFFFFFFu, s1, o);
        }
        if (lane == 0) {
            g_z[rbase + rr]     = d0 / fmaxf(sqrtf(s0), 1e-6f) - 1.0f;
            g_z[rbase + rr + 1] = d1 / fmaxf(sqrtf(s1), 1e-6f) - 1.0f;
        }
    }
}

// ---------------------------------------------------------------------------
// K2: sparsemax via Michelot fixed point. Launch #3.
// ---------------------------------------------------------------------------
__global__ void k2_sparsemax() {
    int b = blockIdx.x, t = threadIdx.x;
    int lane = t & 31, w = t >> 5;             // 16 warps
    __shared__ float sS[16], sK[16];
    __shared__ float s_tau;
    __shared__ int cnt;

    float loc[8];
#pragma unroll
    for (int i = 0; i < 8; i++) loc[i] = g_z[b * NN + t + i * 512];

    float S = 0.f;
#pragma unroll
    for (int i = 0; i < 8; i++) S += loc[i];
#pragma unroll
    for (int o = 16; o; o >>= 1) S += __shfl_xor_sync(0xFFFFFFFFu, S, o);
    if (lane == 0) sS[w] = S;
    __syncthreads();
    if (w == 0) {
        float ss = (lane < 16) ? sS[lane] : 0.f;
#pragma unroll
        for (int o = 8; o; o >>= 1) ss += __shfl_xor_sync(0xFFFFFFFFu, ss, o);
        if (lane == 0) s_tau = (ss - 1.f) / (float)NN;
    }
    __syncthreads();
    float tau = s_tau;

    for (int it = 0; it < 48; it++) {
        float s = 0.f, k = 0.f;
#pragma unroll
        for (int i = 0; i < 8; i++) {
            float v = loc[i];
            if (v > tau) { s += v; k += 1.f; }
        }
#pragma unroll
        for (int o = 16; o; o >>= 1) {
            s += __shfl_xor_sync(0xFFFFFFFFu, s, o);
            k += __shfl_xor_sync(0xFFFFFFFFu, k, o);
        }
        if (lane == 0) { sS[w] = s; sK[w] = k; }
        __syncthreads();
        if (w == 0) {
            float ss = (lane < 16) ? sS[lane] : 0.f;
            float kk = (lane < 16) ? sK[lane] : 0.f;
#pragma unroll
            for (int o = 8; o; o >>= 1) {
                ss += __shfl_xor_sync(0xFFFFFFFFu, ss, o);
                kk += __shfl_xor_sync(0xFFFFFFFFu, kk, o);
            }
            if (lane == 0) s_tau = (ss - 1.f) / kk;
        }
        __syncthreads();
        float tn = s_tau;
        if (!(tn > tau)) break;
        tau = tn;
    }

    if (t == 0) cnt = 0;
    __syncthreads();
#pragma unroll
    for (int i = 0; i < 8; i++) {
        float wv = loc[i] - tau;
        if (wv > 0.f) {
            int p = atomicAdd(&cnt, 1);
            g_nzidx[b * NN + p] = t + i * 512;
            g_nzw[b * NN + p] = wv;
        }
    }
    __syncthreads();
    if (t == 0) g_nnz[b] = cnt;
}

// ---------------------------------------------------------------------------
// K3+K4a merged, grid (64, 18) — launch #4 (profiled):
//   y < 16 : sparse weighted sum (memvec += w * mem rows; MLP=2 pairs)
//   y >= 16: FC1 enc-half GEMM blocks (h1 += enc @ W1[:, 0:1024]^T), which
//            depend on NOTHING from k2/k3 — they fill the gather's SM bubbles.
//            obase = x*64 outputs; K-chunk = (y-16)*512.
// ---------------------------------------------------------------------------
__global__ void __launch_bounds__(256) k3k4a(const float* __restrict__ mem,
                                             const float* __restrict__ enc,
                                             const float* __restrict__ W1) {
    __shared__ float2 sw2[64][33];
    __shared__ float2 sh2[32][33];
    int t = threadIdx.x;

    if (blockIdx.y < 16) {
        // ---- sparse gather (k3) ----
        int b = blockIdx.x, s = blockIdx.y;
        int nnz = g_nnz[b];

        const float4* base = (const float4*)mem + (size_t)b * NN * (DD / 4);
        const int*   idxp = &g_nzidx[b * NN];
        const float* wp   = &g_nzw[b * NN];

        float4 acc = make_float4(0.f, 0.f, 0.f, 0.f);
        int i = s * 2;
        bool any = (i < nnz);
        for (; i + 2 <= nnz; i += 32) {
            int   j0 = idxp[i],   j1 = idxp[i + 1];
            float w0 = wp[i],     w1 = wp[i + 1];
            float4 m0 = __ldcs(&base[(size_t)j0 * (DD / 4) + t]);
            float4 m1 = __ldcs(&base[(size_t)j1 * (DD / 4) + t]);
            acc.x = fmaf(w0, m0.x, fmaf(w1, m1.x, acc.x));
            acc.y = fmaf(w0, m0.y, fmaf(w1, m1.y, acc.y));
            acc.z = fmaf(w0, m0.z, fmaf(w1, m1.z, acc.z));
            acc.w = fmaf(w0, m0.w, fmaf(w1, m1.w, acc.w));
        }
        if (i < nnz) {
            int j = idxp[i];
            float wv = wp[i];
            float4 m = __ldcs(&base[(size_t)j * (DD / 4) + t]);
            acc.x = fmaf(wv, m.x, acc.x);
            acc.y = fmaf(wv, m.y, acc.y);
            acc.z = fmaf(wv, m.z, acc.z);
            acc.w = fmaf(wv, m.w, acc.w);
        }
        if (!any) return;
        float* dst = &g_memvec[b * DD + t * 4];
        atomicAdd(dst + 0, acc.x);
        atomicAdd(dst + 1, acc.y);
        atomicAdd(dst + 2, acc.z);
        atomicAdd(dst + 3, acc.w);
        return;
    }

    // ---- FC1 enc-half GEMM (k4a): independent of k2/k3 ----
    int obase = blockIdx.x * 64;
    int koff = (blockIdx.y - 16) * 512;
    int ol = t & 31;
    int bg = t >> 5;

    ull accA[4] = {0ull, 0ull, 0ull, 0ull};
    ull accB[4] = {0ull, 0ull, 0ull, 0ull};

    for (int kc = koff; kc < koff + 512; kc += 32) {
#pragma unroll
        for (int i = 0; i < 8; i++) {          // 64x32 enc tile
            int e = t + i * 256;
            int row = e >> 5, col = e & 31;
            ((float*)&sh2[row >> 1][col])[row & 1] = enc[row * DD + kc + col];
        }
#pragma unroll
        for (int i = 0; i < 8; i++) {          // 64x32 W tile, splat
            int e = t + i * 256;
            int row = e >> 5, col = e & 31;
            float wv = W1[(size_t)(obase + row) * DIN + kc + col];
            sw2[row][col] = make_float2(wv, wv);
        }
        __syncthreads();
#pragma unroll
        for (int kk = 0; kk < 32; kk++) {
            ull wa = *(const ull*)&sw2[ol][kk];
            ull wb = *(const ull*)&sw2[ol + 32][kk];
#pragma unroll
            for (int j = 0; j < 4; j++) {
                ull h2 = *(const ull*)&sh2[bg * 4 + j][kk];
                asm("fma.rn.f32x2 %0, %1, %2, %0;" : "+l"(accA[j]) : "l"(h2), "l"(wa));
                asm("fma.rn.f32x2 %0, %1, %2, %0;" : "+l"(accB[j]) : "l"(h2), "l"(wb));
            }
        }
        __syncthreads();
    }
    int o0 = obase + ol, o1 = obase + 32 + ol;
#pragma unroll
    for (int j = 0; j < 4; j++) {
        float lo, hi;
        int p = bg * 8 + j * 2;
        asm("mov.b64 {%0, %1}, %2;" : "=f"(lo), "=f"(hi) : "l"(accA[j]));
        atomicAdd(&g_h1[(size_t)p * DHID + o0], lo);
        atomicAdd(&g_h1[(size_t)(p + 1) * DHID + o0], hi);
        asm("mov.b64 {%0, %1}, %2;" : "=f"(lo), "=f"(hi) : "l"(accB[j]));
        atomicAdd(&g_h1[(size_t)p * DHID + o1], lo);
        atomicAdd(&g_h1[(size_t)(p + 1) * DHID + o1], hi);
    }
}

// ---------------------------------------------------------------------------
// K4b: h1 += memvec @ W1[:, 1024:2048]^T. grid (64, 2); K-chunk 512.
//     Launch #5.
// ---------------------------------------------------------------------------
__global__ void k4b_fc1(const float* __restrict__ W1) {
    __shared__ float2 sw2[64][33];
    __shared__ float2 sh2[32][33];
    int t = threadIdx.x;
    int obase = blockIdx.x * 64;
    int koff = blockIdx.y * 512;
    int ol = t & 31;
    int bg = t >> 5;

    ull accA[4] = {0ull, 0ull, 0ull, 0ull};
    ull accB[4] = {0ull, 0ull, 0ull, 0ull};

    for (int kc = koff; kc < koff + 512; kc += 32) {
#pragma unroll
        for (int i = 0; i < 8; i++) {
            int e = t + i * 256;
            int row = e >> 5, col = e & 31;
            ((float*)&sh2[row >> 1][col])[row & 1] = g_memvec[row * DD + kc + col];
        }
#pragma unroll
        for (int i = 0; i < 8; i++) {
            int e = t + i * 256;
            int row = e >> 5, col = e & 31;
            float wv = W1[(size_t)(obase + row) * DIN + DD + kc + col];
            sw2[row][col] = make_float2(wv, wv);
        }
        __syncthreads();
#pragma unroll
        for (int kk = 0; kk < 32; kk++) {
            ull wa = *(const ull*)&sw2[ol][kk];
            ull wb = *(const ull*)&sw2[ol + 32][kk];
#pragma unroll
            for (int j = 0; j < 4; j++) {
                ull h2 = *(const ull*)&sh2[bg * 4 + j][kk];
                asm("fma.rn.f32x2 %0, %1, %2, %0;" : "+l"(accA[j]) : "l"(h2), "l"(wa));
                asm("fma.rn.f32x2 %0, %1, %2, %0;" : "+l"(accB[j]) : "l"(h2), "l"(wb));
            }
        }
        __syncthreads();
    }
    int o0 = obase + ol, o1 = obase + 32 + ol;
#pragma unroll
    for (int j = 0; j < 4; j++) {
        float lo, hi;
        int p = bg * 8 + j * 2;
        asm("mov.b64 {%0, %1}, %2;" : "=f"(lo), "=f"(hi) : "l"(accA[j]));
        atomicAdd(&g_h1[(size_t)p * DHID + o0], lo);
        atomicAdd(&g_h1[(size_t)(p + 1) * DHID + o0], hi);
        asm("mov.b64 {%0, %1}, %2;" : "=f"(lo), "=f"(hi) : "l"(accB[j]));
        atomicAdd(&g_h1[(size_t)p * DHID + o1], lo);
        atomicAdd(&g_h1[(size_t)(p + 1) * DHID + o1], hi);
    }
}

// ---------------------------------------------------------------------------
// K5: out += relu(h1) @ W2^T. grid (16, 8); relu fused; out pre-init by pre.
//     Launch #6.
// ---------------------------------------------------------------------------
__global__ void k5_fc2(const float* __restrict__ W2, float* __restrict__ out) {
    __shared__ float2 sw2[64][33];
    __shared__ float2 sh2[32][33];
    int t = threadIdx.x;
    int obase = blockIdx.x * 64;
    int kbeg = blockIdx.y * (DHID / 8);
    int ol = t & 31;
    int bg = t >> 5;

    ull accA[4] = {0ull, 0ull, 0ull, 0ull};
    ull accB[4] = {0ull, 0ull, 0ull, 0ull};

    for (int kc = kbeg; kc < kbeg + DHID / 8; kc += 32) {
#pragma unroll
        for (int i = 0; i < 8; i++) {
            int e = t + i * 256;
            int row = e >> 5, col = e & 31;
            float v = fmaxf(g_h1[(size_t)row * DHID + kc + col], 0.f);  // relu
            ((float*)&sh2[row >> 1][col])[row & 1] = v;
        }
#pragma unroll
        for (int i = 0; i < 8; i++) {
            int e = t + i * 256;
            int row = e >> 5, col = e & 31;
            int o = obase + row;
            float wv = (o < NOUT) ? W2[(size_t)o * DHID + kc + col] : 0.f;
            sw2[row][col] = make_float2(wv, wv);
        }
        __syncthreads();
#pragma unroll
        for (int kk = 0; kk < 32; kk++) {
            ull wa = *(const ull*)&sw2[ol][kk];
            ull wb = *(const ull*)&sw2[ol + 32][kk];
#pragma unroll
            for (int j = 0; j < 4; j++) {
                ull h2 = *(const ull*)&sh2[bg * 4 + j][kk];
                asm("fma.rn.f32x2 %0, %1, %2, %0;" : "+l"(accA[j]) : "l"(h2), "l"(wa));
                asm("fma.rn.f32x2 %0, %1, %2, %0;" : "+l"(accB[j]) : "l"(h2), "l"(wb));
            }
        }
        __syncthreads();
    }
    int o0 = obase + ol, o1 = obase + 32 + ol;
#pragma unroll
    for (int j = 0; j < 4; j++) {
        float lo, hi;
        int p = bg * 8 + j * 2;
        if (o0 < NOUT) {
            asm("mov.b64 {%0, %1}, %2;" : "=f"(lo), "=f"(hi) : "l"(accA[j]));
            atomicAdd(&out[(size_t)p * NOUT + o0], lo);
            atomicAdd(&out[(size_t)(p + 1) * NOUT + o0], hi);
        }
        if (o1 < NOUT) {
            asm("mov.b64 {%0, %1}, %2;" : "=f"(lo), "=f"(hi) : "l"(accB[j]));
            atomicAdd(&out[(size_t)p * NOUT + o1], lo);
            atomicAdd(&out[(size_t)(p + 1) * NOUT + o1], hi);
        }
    }
}

// ---------------------------------------------------------------------------
extern "C" void kernel_launch(void* const* d_in, const int* in_sizes, int n_in,
                              void* d_out, int out_size) {
    const float* enc = (const float*)d_in[0];   // [64,1024]
    const float* mem = (const float*)d_in[1];   // [64,4096,1024]
    const float* W1  = (const float*)d_in[2];   // [4096,2048]
    const float* b1  = (const float*)d_in[3];   // [4096]
    const float* W2  = (const float*)d_in[4];   // [1000,4096]
    const float* b2  = (const float*)d_in[5];   // [1000]
    float* out = (float*)d_out;                 // [64,1000]

    pre_all<<<1594, 256>>>(enc, b1, b2, out);   // launch 1
    k1_scores<<<(BB * NN) / 64, 256>>>(mem);    // launch 2
    k2_sparsemax<<<BB, 512>>>();                // launch 3
    k3k4a<<<dim3(BB, 18), 256>>>(mem, enc, W1); // launch 4 -> profiled
    k4b_fc1<<<dim3(BB, 2), 256>>>(W1);          // launch 5
    k5_fc2<<<dim3(16, 8), 256>>>(W2, out);      // launch 6
}

// round 11
// speedup vs baseline: 1.1976x; 1.1976x over previous
#include <cuda_runtime.h>
#include <math.h>

#define BB   64
#define NN   4096
#define DD   1024
#define DIN  2048
#define DHID 4096
#define NOUT 1000

typedef unsigned long long ull;

// ---- scratch (device globals; no allocation allowed) ----
__device__ float g_xn[BB * DD];        // normalized encoder
__device__ float g_z[BB * NN];         // sparsemax input scores
__device__ int   g_nzidx[BB * NN];     // compacted support indices
__device__ float g_nzw[BB * NN];       // compacted weights
__device__ int   g_nnz[BB];
__device__ float g_memvec[BB * DD];    // weighted memory readout (atomic acc)
__device__ float g_h1[BB * DHID];      // hidden pre-activations (bias + atomic acc)

// ---------------------------------------------------------------------------
// PRE: blocks [0,64):     xn = enc / max(||enc||,1e-6)
//      blocks [64,1088):  h1 = b1 (bcast)
//      blocks [1088,1344): memvec = 0
//      blocks [1344,1594): out = b2 (bcast)
// ---------------------------------------------------------------------------
__global__ void pre_all(const float* __restrict__ enc,
                        const float* __restrict__ b1,
                        const float* __restrict__ b2,
                        float* __restrict__ out) {
    int bid = blockIdx.x;
    if (bid < 64) {
        int b = bid;
        __shared__ float red[256];
        float ssq = 0.f;
        for (int i = threadIdx.x; i < DD; i += 256) {
            float v = enc[b * DD + i];
            ssq = fmaf(v, v, ssq);
        }
        red[threadIdx.x] = ssq;
        __syncthreads();
        for (int s = 128; s > 0; s >>= 1) {
            if (threadIdx.x < s) red[threadIdx.x] += red[threadIdx.x + s];
            __syncthreads();
        }
        float inv = 1.f / fmaxf(sqrtf(red[0]), 1e-6f);
        for (int i = threadIdx.x; i < DD; i += 256)
            g_xn[b * DD + i] = enc[b * DD + i] * inv;
    } else if (bid < 1088) {
        int i = (bid - 64) * 256 + threadIdx.x;        // BB*DHID
        g_h1[i] = b1[i & (DHID - 1)];
    } else if (bid < 1344) {
        int i = (bid - 1088) * 256 + threadIdx.x;      // BB*DD
        g_memvec[i] = 0.f;
    } else {
        int i = (bid - 1344) * 256 + threadIdx.x;      // BB*NOUT
        if (i < BB * NOUT) out[i] = b2[i % NOUT];
    }
}

// ---------------------------------------------------------------------------
// K1: the 1.07 GB pass (AT DRAM ROOFLINE, 6.63 TB/s — do not touch).
//     Zero smem, MLP=16 per row-pair.
// ---------------------------------------------------------------------------
__global__ void __launch_bounds__(256) k1_scores(const float* __restrict__ mem) {
    int warp = threadIdx.x >> 5, lane = threadIdx.x & 31;
    int rbase = blockIdx.x * 64 + warp * 8;
    int b = rbase >> 12;

    const float4* x4 = (const float4*)g_xn + (size_t)b * (DD / 4);
    float4 x[8];
#pragma unroll
    for (int i = 0; i < 8; i++) x[i] = x4[lane + i * 32];

    const float4* mrow = (const float4*)mem + (size_t)rbase * (DD / 4);

#pragma unroll
    for (int rr = 0; rr < 8; rr += 2) {
        const float4* A = mrow + rr * (DD / 4);
        const float4* C = A + (DD / 4);
        float4 a[8], c[8];
#pragma unroll
        for (int i = 0; i < 8; i++) {
            a[i] = __ldcs(&A[lane + i * 32]);
            c[i] = __ldcs(&C[lane + i * 32]);
        }
        float d0 = 0.f, s0 = 0.f, d1 = 0.f, s1 = 0.f;
#pragma unroll
        for (int i = 0; i < 8; i++) {
            float4 xv = x[i];
            d0 = fmaf(a[i].x, xv.x, fmaf(a[i].y, xv.y, fmaf(a[i].z, xv.z, fmaf(a[i].w, xv.w, d0))));
            s0 = fmaf(a[i].x, a[i].x, fmaf(a[i].y, a[i].y, fmaf(a[i].z, a[i].z, fmaf(a[i].w, a[i].w, s0))));
            d1 = fmaf(c[i].x, xv.x, fmaf(c[i].y, xv.y, fmaf(c[i].z, xv.z, fmaf(c[i].w, xv.w, d1))));
            s1 = fmaf(c[i].x, c[i].x, fmaf(c[i].y, c[i].y, fmaf(c[i].z, c[i].z, fmaf(c[i].w, c[i].w, s1))));
        }
#pragma unroll
        for (int o = 16; o; o >>= 1) {
            d0 += __shfl_xor_sync(0xFFFFFFFFu, d0, o);
            s0 += __shfl_xor_sync(0xFFFFFFFFu, s0, o);
            d1 += __shfl_xor_sync(0xFFFFFFFFu, d1, o);
            s1 += __shfl_xor_sync(0xFFFFFFFFu, s1, o);
        }
        if (lane == 0) {
            g_z[rbase + rr]     = d0 / fmaxf(sqrtf(s0), 1e-6f) - 1.0f;
            g_z[rbase + rr + 1] = d1 / fmaxf(sqrtf(s1), 1e-6f) - 1.0f;
        }
    }
}

// ---------------------------------------------------------------------------
// K2: sparsemax via Michelot fixed point. 64 blocks x 512, 8 elems/thread.
// ---------------------------------------------------------------------------
__global__ void k2_sparsemax() {
    int b = blockIdx.x, t = threadIdx.x;
    int lane = t & 31, w = t >> 5;             // 16 warps
    __shared__ float sS[16], sK[16];
    __shared__ float s_tau;
    __shared__ int cnt;

    float loc[8];
#pragma unroll
    for (int i = 0; i < 8; i++) loc[i] = g_z[b * NN + t + i * 512];

    float S = 0.f;
#pragma unroll
    for (int i = 0; i < 8; i++) S += loc[i];
#pragma unroll
    for (int o = 16; o; o >>= 1) S += __shfl_xor_sync(0xFFFFFFFFu, S, o);
    if (lane == 0) sS[w] = S;
    __syncthreads();
    if (w == 0) {
        float ss = (lane < 16) ? sS[lane] : 0.f;
#pragma unroll
        for (int o = 8; o; o >>= 1) ss += __shfl_xor_sync(0xFFFFFFFFu, ss, o);
        if (lane == 0) s_tau = (ss - 1.f) / (float)NN;
    }
    __syncthreads();
    float tau = s_tau;

    for (int it = 0; it < 48; it++) {
        float s = 0.f, k = 0.f;
#pragma unroll
        for (int i = 0; i < 8; i++) {
            float v = loc[i];
            if (v > tau) { s += v; k += 1.f; }
        }
#pragma unroll
        for (int o = 16; o; o >>= 1) {
            s += __shfl_xor_sync(0xFFFFFFFFu, s, o);
            k += __shfl_xor_sync(0xFFFFFFFFu, k, o);
        }
        if (lane == 0) { sS[w] = s; sK[w] = k; }
        __syncthreads();
        if (w == 0) {
            float ss = (lane < 16) ? sS[lane] : 0.f;
            float kk = (lane < 16) ? sK[lane] : 0.f;
#pragma unroll
            for (int o = 8; o; o >>= 1) {
                ss += __shfl_xor_sync(0xFFFFFFFFu, ss, o);
                kk += __shfl_xor_sync(0xFFFFFFFFu, kk, o);
            }
            if (lane == 0) s_tau = (ss - 1.f) / kk;
        }
        __syncthreads();
        float tn = s_tau;
        if (!(tn > tau)) break;
        tau = tn;
    }

    if (t == 0) cnt = 0;
    __syncthreads();
#pragma unroll
    for (int i = 0; i < 8; i++) {
        float wv = loc[i] - tau;
        if (wv > 0.f) {
            int p = atomicAdd(&cnt, 1);
            g_nzidx[b * NN + p] = t + i * 512;
            g_nzw[b * NN + p] = wv;
        }
    }
    __syncthreads();
    if (t == 0) g_nnz[b] = cnt;
}

// ---------------------------------------------------------------------------
// K3: memvec[b,:] += sum over interleaved support pairs of w * mem[b,idx,:]
//     grid (64, 16): proven-best; pair-unroll (MLP=2), ~30 regs.
// ---------------------------------------------------------------------------
__global__ void __launch_bounds__(256) k3_weighted_sum(const float* __restrict__ mem) {
    int b = blockIdx.x, s = blockIdx.y, t = threadIdx.x;
    int nnz = g_nnz[b];

    const float4* base = (const float4*)mem + (size_t)b * NN * (DD / 4);
    const int*   idxp = &g_nzidx[b * NN];
    const float* wp   = &g_nzw[b * NN];

    float4 acc = make_float4(0.f, 0.f, 0.f, 0.f);
    int i = s * 2;
    bool any = (i < nnz);
    for (; i + 2 <= nnz; i += 32) {
        int   j0 = idxp[i],   j1 = idxp[i + 1];
        float w0 = wp[i],     w1 = wp[i + 1];
        float4 m0 = __ldcs(&base[(size_t)j0 * (DD / 4) + t]);
        float4 m1 = __ldcs(&base[(size_t)j1 * (DD / 4) + t]);
        acc.x = fmaf(w0, m0.x, fmaf(w1, m1.x, acc.x));
        acc.y = fmaf(w0, m0.y, fmaf(w1, m1.y, acc.y));
        acc.z = fmaf(w0, m0.z, fmaf(w1, m1.z, acc.z));
        acc.w = fmaf(w0, m0.w, fmaf(w1, m1.w, acc.w));
    }
    if (i < nnz) {
        int j = idxp[i];
        float wv = wp[i];
        float4 m = __ldcs(&base[(size_t)j * (DD / 4) + t]);
        acc.x = fmaf(wv, m.x, acc.x);
        acc.y = fmaf(wv, m.y, acc.y);
        acc.z = fmaf(wv, m.z, acc.z);
        acc.w = fmaf(wv, m.w, acc.w);
    }
    if (!any) return;
    float* dst = &g_memvec[b * DD + t * 4];
    atomicAdd(dst + 0, acc.x);
    atomicAdd(dst + 1, acc.y);
    atomicAdd(dst + 2, acc.z);
    atomicAdd(dst + 3, acc.w);
}

// ---------------------------------------------------------------------------
// K4a (STREAM 2, concurrent with k1/k2/k3):
//     h1 += enc @ W1[:, 0:1024]^T   — depends only on pre_all (h1=b1 init).
//     grid (64, 2); 64-out x 64-batch tiles, K-chunk 512.
// ---------------------------------------------------------------------------
__global__ void k4a_fc1(const float* __restrict__ enc,
                        const float* __restrict__ W1) {
    __shared__ float2 sw2[64][33];
    __shared__ float2 sh2[32][33];
    int t = threadIdx.x;
    int obase = blockIdx.x * 64;
    int koff = blockIdx.y * 512;
    int ol = t & 31;
    int bg = t >> 5;

    ull accA[4] = {0ull, 0ull, 0ull, 0ull};
    ull accB[4] = {0ull, 0ull, 0ull, 0ull};

    for (int kc = koff; kc < koff + 512; kc += 32) {
#pragma unroll
        for (int i = 0; i < 8; i++) {
            int e = t + i * 256;
            int row = e >> 5, col = e & 31;
            ((float*)&sh2[row >> 1][col])[row & 1] = enc[row * DD + kc + col];
        }
#pragma unroll
        for (int i = 0; i < 8; i++) {
            int e = t + i * 256;
            int row = e >> 5, col = e & 31;
            float wv = W1[(size_t)(obase + row) * DIN + kc + col];
            sw2[row][col] = make_float2(wv, wv);
        }
        __syncthreads();
#pragma unroll
        for (int kk = 0; kk < 32; kk++) {
            ull wa = *(const ull*)&sw2[ol][kk];
            ull wb = *(const ull*)&sw2[ol + 32][kk];
#pragma unroll
            for (int j = 0; j < 4; j++) {
                ull h2 = *(const ull*)&sh2[bg * 4 + j][kk];
                asm("fma.rn.f32x2 %0, %1, %2, %0;" : "+l"(accA[j]) : "l"(h2), "l"(wa));
                asm("fma.rn.f32x2 %0, %1, %2, %0;" : "+l"(accB[j]) : "l"(h2), "l"(wb));
            }
        }
        __syncthreads();
    }
    int o0 = obase + ol, o1 = obase + 32 + ol;
#pragma unroll
    for (int j = 0; j < 4; j++) {
        float lo, hi;
        int p = bg * 8 + j * 2;
        asm("mov.b64 {%0, %1}, %2;" : "=f"(lo), "=f"(hi) : "l"(accA[j]));
        atomicAdd(&g_h1[(size_t)p * DHID + o0], lo);
        atomicAdd(&g_h1[(size_t)(p + 1) * DHID + o0], hi);
        asm("mov.b64 {%0, %1}, %2;" : "=f"(lo), "=f"(hi) : "l"(accB[j]));
        atomicAdd(&g_h1[(size_t)p * DHID + o1], lo);
        atomicAdd(&g_h1[(size_t)(p + 1) * DHID + o1], hi);
    }
}

// ---------------------------------------------------------------------------
// K4b (main stream, after k3): h1 += memvec @ W1[:, 1024:2048]^T. grid (64,2).
// ---------------------------------------------------------------------------
__global__ void k4b_fc1(const float* __restrict__ W1) {
    __shared__ float2 sw2[64][33];
    __shared__ float2 sh2[32][33];
    int t = threadIdx.x;
    int obase = blockIdx.x * 64;
    int koff = blockIdx.y * 512;
    int ol = t & 31;
    int bg = t >> 5;

    ull accA[4] = {0ull, 0ull, 0ull, 0ull};
    ull accB[4] = {0ull, 0ull, 0ull, 0ull};

    for (int kc = koff; kc < koff + 512; kc += 32) {
#pragma unroll
        for (int i = 0; i < 8; i++) {
            int e = t + i * 256;
            int row = e >> 5, col = e & 31;
            ((float*)&sh2[row >> 1][col])[row & 1] = g_memvec[row * DD + kc + col];
        }
#pragma unroll
        for (int i = 0; i < 8; i++) {
            int e = t + i * 256;
            int row = e >> 5, col = e & 31;
            float wv = W1[(size_t)(obase + row) * DIN + DD + kc + col];
            sw2[row][col] = make_float2(wv, wv);
        }
        __syncthreads();
#pragma unroll
        for (int kk = 0; kk < 32; kk++) {
            ull wa = *(const ull*)&sw2[ol][kk];
            ull wb = *(const ull*)&sw2[ol + 32][kk];
#pragma unroll
            for (int j = 0; j < 4; j++) {
                ull h2 = *(const ull*)&sh2[bg * 4 + j][kk];
                asm("fma.rn.f32x2 %0, %1, %2, %0;" : "+l"(accA[j]) : "l"(h2), "l"(wa));
                asm("fma.rn.f32x2 %0, %1, %2, %0;" : "+l"(accB[j]) : "l"(h2), "l"(wb));
            }
        }
        __syncthreads();
    }
    int o0 = obase + ol, o1 = obase + 32 + ol;
#pragma unroll
    for (int j = 0; j < 4; j++) {
        float lo, hi;
        int p = bg * 8 + j * 2;
        asm("mov.b64 {%0, %1}, %2;" : "=f"(lo), "=f"(hi) : "l"(accA[j]));
        atomicAdd(&g_h1[(size_t)p * DHID + o0], lo);
        atomicAdd(&g_h1[(size_t)(p + 1) * DHID + o0], hi);
        asm("mov.b64 {%0, %1}, %2;" : "=f"(lo), "=f"(hi) : "l"(accB[j]));
        atomicAdd(&g_h1[(size_t)p * DHID + o1], lo);
        atomicAdd(&g_h1[(size_t)(p + 1) * DHID + o1], hi);
    }
}

// ---------------------------------------------------------------------------
// K5: out += relu(h1) @ W2^T. grid (16, 8); relu fused; out pre-init by pre.
// ---------------------------------------------------------------------------
__global__ void k5_fc2(const float* __restrict__ W2, float* __restrict__ out) {
    __shared__ float2 sw2[64][33];
    __shared__ float2 sh2[32][33];
    int t = threadIdx.x;
    int obase = blockIdx.x * 64;
    int kbeg = blockIdx.y * (DHID / 8);
    int ol = t & 31;
    int bg = t >> 5;

    ull accA[4] = {0ull, 0ull, 0ull, 0ull};
    ull accB[4] = {0ull, 0ull, 0ull, 0ull};

    for (int kc = kbeg; kc < kbeg + DHID / 8; kc += 32) {
#pragma unroll
        for (int i = 0; i < 8; i++) {
            int e = t + i * 256;
            int row = e >> 5, col = e & 31;
            float v = fmaxf(g_h1[(size_t)row * DHID + kc + col], 0.f);  // relu
            ((float*)&sh2[row >> 1][col])[row & 1] = v;
        }
#pragma unroll
        for (int i = 0; i < 8; i++) {
            int e = t + i * 256;
            int row = e >> 5, col = e & 31;
            int o = obase + row;
            float wv = (o < NOUT) ? W2[(size_t)o * DHID + kc + col] : 0.f;
            sw2[row][col] = make_float2(wv, wv);
        }
        __syncthreads();
#pragma unroll
        for (int kk = 0; kk < 32; kk++) {
            ull wa = *(const ull*)&sw2[ol][kk];
            ull wb = *(const ull*)&sw2[ol + 32][kk];
#pragma unroll
            for (int j = 0; j < 4; j++) {
                ull h2 = *(const ull*)&sh2[bg * 4 + j][kk];
                asm("fma.rn.f32x2 %0, %1, %2, %0;" : "+l"(accA[j]) : "l"(h2), "l"(wa));
                asm("fma.rn.f32x2 %0, %1, %2, %0;" : "+l"(accB[j]) : "l"(h2), "l"(wb));
            }
        }
        __syncthreads();
    }
    int o0 = obase + ol, o1 = obase + 32 + ol;
#pragma unroll
    for (int j = 0; j < 4; j++) {
        float lo, hi;
        int p = bg * 8 + j * 2;
        if (o0 < NOUT) {
            asm("mov.b64 {%0, %1}, %2;" : "=f"(lo), "=f"(hi) : "l"(accA[j]));
            atomicAdd(&out[(size_t)p * NOUT + o0], lo);
            atomicAdd(&out[(size_t)(p + 1) * NOUT + o0], hi);
        }
        if (o1 < NOUT) {
            asm("mov.b64 {%0, %1}, %2;" : "=f"(lo), "=f"(hi) : "l"(accB[j]));
            atomicAdd(&out[(size_t)p * NOUT + o1], lo);
            atomicAdd(&out[(size_t)(p + 1) * NOUT + o1], hi);
        }
    }
}

// ---------------------------------------------------------------------------
// Lazy side-stream / events: created on the FIRST call (the correctness run,
// which is NOT under graph capture). During capture they are only used
// (record/wait), which is the standard capturable fork/join pattern.
// ---------------------------------------------------------------------------
static cudaStream_t side_stream() {
    static cudaStream_t s = [] {
        cudaStream_t t;
        cudaStreamCreateWithFlags(&t, cudaStreamNonBlocking);
        return t;
    }();
    return s;
}
static cudaEvent_t fork_event() {
    static cudaEvent_t e = [] {
        cudaEvent_t t;
        cudaEventCreateWithFlags(&t, cudaEventDisableTiming);
        return t;
    }();
    return e;
}
static cudaEvent_t join_event() {
    static cudaEvent_t e = [] {
        cudaEvent_t t;
        cudaEventCreateWithFlags(&t, cudaEventDisableTiming);
        return t;
    }();
    return e;
}

// ---------------------------------------------------------------------------
extern "C" void kernel_launch(void* const* d_in, const int* in_sizes, int n_in,
                              void* d_out, int out_size) {
    const float* enc = (const float*)d_in[0];   // [64,1024]
    const float* mem = (const float*)d_in[1];   // [64,4096,1024]
    const float* W1  = (const float*)d_in[2];   // [4096,2048]
    const float* b1  = (const float*)d_in[3];   // [4096]
    const float* W2  = (const float*)d_in[4];   // [1000,4096]
    const float* b2  = (const float*)d_in[5];   // [1000]
    float* out = (float*)d_out;                 // [64,1000]

    cudaStream_t s2 = side_stream();
    cudaEvent_t evF = fork_event();
    cudaEvent_t evJ = join_event();

    // main stream: full dependency chain
    pre_all<<<1594, 256>>>(enc, b1, b2, out);

    // fork: k4a (enc-half FC1) runs concurrently with k1/k2/k3
    cudaEventRecord(evF, 0);
    cudaStreamWaitEvent(s2, evF, 0);
    k4a_fc1<<<dim3(BB, 2), 256, 0, s2>>>(enc, W1);
    cudaEventRecord(evJ, s2);

    k1_scores<<<(BB * NN) / 64, 256>>>(mem);
    k2_sparsemax<<<BB, 512>>>();
    k3_weighted_sum<<<dim3(BB, 16), 256>>>(mem);
    k4b_fc1<<<dim3(BB, 2), 256>>>(W1);

    // join: k5 needs h1 complete (k4a + k4b)
    cudaStreamWaitEvent(0, evJ, 0);
    k5_fc2<<<dim3(16, 8), 256>>>(W2, out);
}

// round 12
// speedup vs baseline: 1.2127x; 1.0126x over previous
#include <cuda_runtime.h>
#include <math.h>

#define BB   64
#define NN   4096
#define DD   1024
#define DIN  2048
#define DHID 4096
#define NOUT 1000

typedef unsigned long long ull;

// ---- scratch (device globals; no allocation allowed) ----
__device__ float g_xn[BB * DD];        // normalized encoder
__device__ float g_z[BB * NN];         // sparsemax input scores
__device__ int   g_nzidx[BB * NN];     // compacted support indices
__device__ float g_nzw[BB * NN];       // compacted weights
__device__ int   g_nnz[BB];
__device__ float g_memvec[BB * DD];    // weighted memory readout (atomic acc)
__device__ float g_h1[BB * DHID];      // hidden pre-activations (bias + atomic acc)
__device__ float g_sink;               // DCE-blocker for the L2 warm kernel

// ---------------------------------------------------------------------------
// PRE: blocks [0,64):     xn = enc / max(||enc||,1e-6)
//      blocks [64,1088):  h1 = b1 (bcast)
//      blocks [1088,1344): memvec = 0
//      blocks [1344,1594): out = b2 (bcast)
// ---------------------------------------------------------------------------
__global__ void pre_all(const float* __restrict__ enc,
                        const float* __restrict__ b1,
                        const float* __restrict__ b2,
                        float* __restrict__ out) {
    int bid = blockIdx.x;
    if (bid < 64) {
        int b = bid;
        __shared__ float red[256];
        float ssq = 0.f;
        for (int i = threadIdx.x; i < DD; i += 256) {
            float v = enc[b * DD + i];
            ssq = fmaf(v, v, ssq);
        }
        red[threadIdx.x] = ssq;
        __syncthreads();
        for (int s = 128; s > 0; s >>= 1) {
            if (threadIdx.x < s) red[threadIdx.x] += red[threadIdx.x + s];
            __syncthreads();
        }
        float inv = 1.f / fmaxf(sqrtf(red[0]), 1e-6f);
        for (int i = threadIdx.x; i < DD; i += 256)
            g_xn[b * DD + i] = enc[b * DD + i] * inv;
    } else if (bid < 1088) {
        int i = (bid - 64) * 256 + threadIdx.x;        // BB*DHID
        g_h1[i] = b1[i & (DHID - 1)];
    } else if (bid < 1344) {
        int i = (bid - 1088) * 256 + threadIdx.x;      // BB*DD
        g_memvec[i] = 0.f;
    } else {
        int i = (bid - 1344) * 256 + threadIdx.x;      // BB*NOUT
        if (i < BB * NOUT) out[i] = b2[i % NOUT];
    }
}

// ---------------------------------------------------------------------------
// K1: the 1.07 GB pass (AT DRAM ROOFLINE, 6.63 TB/s — do not touch).
// ---------------------------------------------------------------------------
__global__ void __launch_bounds__(256) k1_scores(const float* __restrict__ mem) {
    int warp = threadIdx.x >> 5, lane = threadIdx.x & 31;
    int rbase = blockIdx.x * 64 + warp * 8;
    int b = rbase >> 12;

    const float4* x4 = (const float4*)g_xn + (size_t)b * (DD / 4);
    float4 x[8];
#pragma unroll
    for (int i = 0; i < 8; i++) x[i] = x4[lane + i * 32];

    const float4* mrow = (const float4*)mem + (size_t)rbase * (DD / 4);

#pragma unroll
    for (int rr = 0; rr < 8; rr += 2) {
        const float4* A = mrow + rr * (DD / 4);
        const float4* C = A + (DD / 4);
        float4 a[8], c[8];
#pragma unroll
        for (int i = 0; i < 8; i++) {
            a[i] = __ldcs(&A[lane + i * 32]);
            c[i] = __ldcs(&C[lane + i * 32]);
        }
        float d0 = 0.f, s0 = 0.f, d1 = 0.f, s1 = 0.f;
#pragma unroll
        for (int i = 0; i < 8; i++) {
            float4 xv = x[i];
            d0 = fmaf(a[i].x, xv.x, fmaf(a[i].y, xv.y, fmaf(a[i].z, xv.z, fmaf(a[i].w, xv.w, d0))));
            s0 = fmaf(a[i].x, a[i].x, fmaf(a[i].y, a[i].y, fmaf(a[i].z, a[i].z, fmaf(a[i].w, a[i].w, s0))));
            d1 = fmaf(c[i].x, xv.x, fmaf(c[i].y, xv.y, fmaf(c[i].z, xv.z, fmaf(c[i].w, xv.w, d1))));
            s1 = fmaf(c[i].x, c[i].x, fmaf(c[i].y, c[i].y, fmaf(c[i].z, c[i].z, fmaf(c[i].w, c[i].w, s1))));
        }
#pragma unroll
        for (int o = 16; o; o >>= 1) {
            d0 += __shfl_xor_sync(0xFFFFFFFFu, d0, o);
            s0 += __shfl_xor_sync(0xFFFFFFFFu, s0, o);
            d1 += __shfl_xor_sync(0xFFFFFFFFu, d1, o);
            s1 += __shfl_xor_sync(0xFFFFFFFFu, s1, o);
        }
        if (lane == 0) {
            g_z[rbase + rr]     = d0 / fmaxf(sqrtf(s0), 1e-6f) - 1.0f;
            g_z[rbase + rr + 1] = d1 / fmaxf(sqrtf(s1), 1e-6f) - 1.0f;
        }
    }
}

// ---------------------------------------------------------------------------
// K2: sparsemax via Michelot fixed point. Parity-buffered smem partials:
//     ONE barrier per iteration, redundant all-warp final reduce.
//     64 blocks x 512 threads, 8 elems/thread.
// ---------------------------------------------------------------------------
__global__ void k2_sparsemax() {
    int b = blockIdx.x, t = threadIdx.x;
    int lane = t & 31, w = t >> 5;             // 16 warps
    __shared__ float sS[2][16], sK[2][16];
    __shared__ int cnt;

    float loc[8];
#pragma unroll
    for (int i = 0; i < 8; i++) loc[i] = g_z[b * NN + t + i * 512];

    // initial tau = (sum - 1)/N
    float S = 0.f;
#pragma unroll
    for (int i = 0; i < 8; i++) S += loc[i];
#pragma unroll
    for (int o = 16; o; o >>= 1) S += __shfl_xor_sync(0xFFFFFFFFu, S, o);
    if (lane == 0) sS[0][w] = S;
    __syncthreads();
    float tau;
    {
        float ss = 0.f;
#pragma unroll
        for (int i = 0; i < 16; i++) ss += sS[0][i];
        tau = (ss - 1.f) / (float)NN;
    }

    int par = 1;
    for (int it = 0; it < 48; it++) {
        float s = 0.f, k = 0.f;
#pragma unroll
        for (int i = 0; i < 8; i++) {
            float v = loc[i];
            if (v > tau) { s += v; k += 1.f; }
        }
#pragma unroll
        for (int o = 16; o; o >>= 1) {
            s += __shfl_xor_sync(0xFFFFFFFFu, s, o);
            k += __shfl_xor_sync(0xFFFFFFFFu, k, o);
        }
        if (lane == 0) { sS[par][w] = s; sK[par][w] = k; }
        __syncthreads();
        float ss = 0.f, kk = 0.f;
#pragma unroll
        for (int i = 0; i < 16; i++) { ss += sS[par][i]; kk += sK[par][i]; }
        float tn = (ss - 1.f) / kk;        // identical in all threads
        if (!(tn > tau)) break;            // uniform decision
        tau = tn;
        par ^= 1;
    }

    if (t == 0) cnt = 0;
    __syncthreads();
#pragma unroll
    for (int i = 0; i < 8; i++) {
        float wv = loc[i] - tau;
        if (wv > 0.f) {
            int p = atomicAdd(&cnt, 1);
            g_nzidx[b * NN + p] = t + i * 512;
            g_nzw[b * NN + p] = wv;
        }
    }
    __syncthreads();
    if (t == 0) g_nnz[b] = cnt;
}

// ---------------------------------------------------------------------------
// K3: memvec[b,:] += sum over interleaved support pairs of w * mem[b,idx,:]
//     grid (64, 16): proven-best; pair-unroll (MLP=2), ~30 regs.
// ---------------------------------------------------------------------------
__global__ void __launch_bounds__(256) k3_weighted_sum(const float* __restrict__ mem) {
    int b = blockIdx.x, s = blockIdx.y, t = threadIdx.x;
    int nnz = g_nnz[b];

    const float4* base = (const float4*)mem + (size_t)b * NN * (DD / 4);
    const int*   idxp = &g_nzidx[b * NN];
    const float* wp   = &g_nzw[b * NN];

    float4 acc = make_float4(0.f, 0.f, 0.f, 0.f);
    int i = s * 2;
    bool any = (i < nnz);
    for (; i + 2 <= nnz; i += 32) {
        int   j0 = idxp[i],   j1 = idxp[i + 1];
        float w0 = wp[i],     w1 = wp[i + 1];
        float4 m0 = __ldcs(&base[(size_t)j0 * (DD / 4) + t]);
        float4 m1 = __ldcs(&base[(size_t)j1 * (DD / 4) + t]);
        acc.x = fmaf(w0, m0.x, fmaf(w1, m1.x, acc.x));
        acc.y = fmaf(w0, m0.y, fmaf(w1, m1.y, acc.y));
        acc.z = fmaf(w0, m0.z, fmaf(w1, m1.z, acc.z));
        acc.w = fmaf(w0, m0.w, fmaf(w1, m1.w, acc.w));
    }
    if (i < nnz) {
        int j = idxp[i];
        float wv = wp[i];
        float4 m = __ldcs(&base[(size_t)j * (DD / 4) + t]);
        acc.x = fmaf(wv, m.x, acc.x);
        acc.y = fmaf(wv, m.y, acc.y);
        acc.z = fmaf(wv, m.z, acc.z);
        acc.w = fmaf(wv, m.w, acc.w);
    }
    if (!any) return;
    float* dst = &g_memvec[b * DD + t * 4];
    atomicAdd(dst + 0, acc.x);
    atomicAdd(dst + 1, acc.y);
    atomicAdd(dst + 2, acc.z);
    atomicAdd(dst + 3, acc.w);
}

// ---------------------------------------------------------------------------
// K4a (STREAM 2, concurrent with k1/k2/k3):
//     h1 += enc @ W1[:, 0:1024]^T   — depends only on pre_all (h1=b1 init).
// ---------------------------------------------------------------------------
__global__ void k4a_fc1(const float* __restrict__ enc,
                        const float* __restrict__ W1) {
    __shared__ float2 sw2[64][33];
    __shared__ float2 sh2[32][33];
    int t = threadIdx.x;
    int obase = blockIdx.x * 64;
    int koff = blockIdx.y * 512;
    int ol = t & 31;
    int bg = t >> 5;

    ull accA[4] = {0ull, 0ull, 0ull, 0ull};
    ull accB[4] = {0ull, 0ull, 0ull, 0ull};

    for (int kc = koff; kc < koff + 512; kc += 32) {
#pragma unroll
        for (int i = 0; i < 8; i++) {
            int e = t + i * 256;
            int row = e >> 5, col = e & 31;
            ((float*)&sh2[row >> 1][col])[row & 1] = enc[row * DD + kc + col];
        }
#pragma unroll
        for (int i = 0; i < 8; i++) {
            int e = t + i * 256;
            int row = e >> 5, col = e & 31;
            float wv = W1[(size_t)(obase + row) * DIN + kc + col];
            sw2[row][col] = make_float2(wv, wv);
        }
        __syncthreads();
#pragma unroll
        for (int kk = 0; kk < 32; kk++) {
            ull wa = *(const ull*)&sw2[ol][kk];
            ull wb = *(const ull*)&sw2[ol + 32][kk];
#pragma unroll
            for (int j = 0; j < 4; j++) {
                ull h2 = *(const ull*)&sh2[bg * 4 + j][kk];
                asm("fma.rn.f32x2 %0, %1, %2, %0;" : "+l"(accA[j]) : "l"(h2), "l"(wa));
                asm("fma.rn.f32x2 %0, %1, %2, %0;" : "+l"(accB[j]) : "l"(h2), "l"(wb));
            }
        }
        __syncthreads();
    }
    int o0 = obase + ol, o1 = obase + 32 + ol;
#pragma unroll
    for (int j = 0; j < 4; j++) {
        float lo, hi;
        int p = bg * 8 + j * 2;
        asm("mov.b64 {%0, %1}, %2;" : "=f"(lo), "=f"(hi) : "l"(accA[j]));
        atomicAdd(&g_h1[(size_t)p * DHID + o0], lo);
        atomicAdd(&g_h1[(size_t)(p + 1) * DHID + o0], hi);
        asm("mov.b64 {%0, %1}, %2;" : "=f"(lo), "=f"(hi) : "l"(accB[j]));
        atomicAdd(&g_h1[(size_t)p * DHID + o1], lo);
        atomicAdd(&g_h1[(size_t)(p + 1) * DHID + o1], hi);
    }
}

// ---------------------------------------------------------------------------
// WARM (STREAM 2, after k4a, still under k1): touch W1[:,1024:2048] and W2
//     via __ldcg so k4b/k5 hit L2 instead of DRAM. k1's __ldcs stream is
//     evict-first, so these 32 MB should survive in the 126 MB L2.
//     grid 3048 x 256: blocks [0,2048) -> W1b (2 rows each);
//                      blocks [2048,3048) -> W2 (1 row each).
// ---------------------------------------------------------------------------
__global__ void l2_warm(const float* __restrict__ W1,
                        const float* __restrict__ W2) {
    int t = threadIdx.x;
    float acc = 0.f;
    if (blockIdx.x < 2048) {
        int row = blockIdx.x * 2;
#pragma unroll
        for (int r = 0; r < 2; r++) {
            const float4* p = (const float4*)(W1 + (size_t)(row + r) * DIN + DD);
            float4 v = __ldcg(&p[t]);          // 256 thr x 16B = 1024 floats
            acc += v.x + v.y + v.z + v.w;
        }
    } else {
        int row = blockIdx.x - 2048;           // 0..999
        const float4* p = (const float4*)(W2 + (size_t)row * DHID);
#pragma unroll
        for (int r = 0; r < 4; r++) {
            float4 v = __ldcg(&p[t + r * 256]);
            acc += v.x + v.y + v.z + v.w;
        }
    }
    if (acc == 1.23456789e+30f) g_sink = acc;  // never true; keeps the loads
}

// ---------------------------------------------------------------------------
// K4b (main stream, after k3): h1 += memvec @ W1[:, 1024:2048]^T. grid (64,2).
// ---------------------------------------------------------------------------
__global__ void k4b_fc1(const float* __restrict__ W1) {
    __shared__ float2 sw2[64][33];
    __shared__ float2 sh2[32][33];
    int t = threadIdx.x;
    int obase = blockIdx.x * 64;
    int koff = blockIdx.y * 512;
    int ol = t & 31;
    int bg = t >> 5;

    ull accA[4] = {0ull, 0ull, 0ull, 0ull};
    ull accB[4] = {0ull, 0ull, 0ull, 0ull};

    for (int kc = koff; kc < koff + 512; kc += 32) {
#pragma unroll
        for (int i = 0; i < 8; i++) {
            int e = t + i * 256;
            int row = e >> 5, col = e & 31;
            ((float*)&sh2[row >> 1][col])[row & 1] = g_memvec[row * DD + kc + col];
        }
#pragma unroll
        for (int i = 0; i < 8; i++) {
            int e = t + i * 256;
            int row = e >> 5, col = e & 31;
            float wv = W1[(size_t)(obase + row) * DIN + DD + kc + col];
            sw2[row][col] = make_float2(wv, wv);
        }
        __syncthreads();
#pragma unroll
        for (int kk = 0; kk < 32; kk++) {
            ull wa = *(const ull*)&sw2[ol][kk];
            ull wb = *(const ull*)&sw2[ol + 32][kk];
#pragma unroll
            for (int j = 0; j < 4; j++) {
                ull h2 = *(const ull*)&sh2[bg * 4 + j][kk];
                asm("fma.rn.f32x2 %0, %1, %2, %0;" : "+l"(accA[j]) : "l"(h2), "l"(wa));
                asm("fma.rn.f32x2 %0, %1, %2, %0;" : "+l"(accB[j]) : "l"(h2), "l"(wb));
            }
        }
        __syncthreads();
    }
    int o0 = obase + ol, o1 = obase + 32 + ol;
#pragma unroll
    for (int j = 0; j < 4; j++) {
        float lo, hi;
        int p = bg * 8 + j * 2;
        asm("mov.b64 {%0, %1}, %2;" : "=f"(lo), "=f"(hi) : "l"(accA[j]));
        atomicAdd(&g_h1[(size_t)p * DHID + o0], lo);
        atomicAdd(&g_h1[(size_t)(p + 1) * DHID + o0], hi);
        asm("mov.b64 {%0, %1}, %2;" : "=f"(lo), "=f"(hi) : "l"(accB[j]));
        atomicAdd(&g_h1[(size_t)p * DHID + o1], lo);
        atomicAdd(&g_h1[(size_t)(p + 1) * DHID + o1], hi);
    }
}

// ---------------------------------------------------------------------------
// K5: out += relu(h1) @ W2^T. grid (16, 8); relu fused; out pre-init by pre.
// ---------------------------------------------------------------------------
__global__ void k5_fc2(const float* __restrict__ W2, float* __restrict__ out) {
    __shared__ float2 sw2[64][33];
    __shared__ float2 sh2[32][33];
    int t = threadIdx.x;
    int obase = blockIdx.x * 64;
    int kbeg = blockIdx.y * (DHID / 8);
    int ol = t & 31;
    int bg = t >> 5;

    ull accA[4] = {0ull, 0ull, 0ull, 0ull};
    ull accB[4] = {0ull, 0ull, 0ull, 0ull};

    for (int kc = kbeg; kc < kbeg + DHID / 8; kc += 32) {
#pragma unroll
        for (int i = 0; i < 8; i++) {
            int e = t + i * 256;
            int row = e >> 5, col = e & 31;
            float v = fmaxf(g_h1[(size_t)row * DHID + kc + col], 0.f);  // relu
            ((float*)&sh2[row >> 1][col])[row & 1] = v;
        }
#pragma unroll
        for (int i = 0; i < 8; i++) {
            int e = t + i * 256;
            int row = e >> 5, col = e & 31;
            int o = obase + row;
            float wv = (o < NOUT) ? W2[(size_t)o * DHID + kc + col] : 0.f;
            sw2[row][col] = make_float2(wv, wv);
        }
        __syncthreads();
#pragma unroll
        for (int kk = 0; kk < 32; kk++) {
            ull wa = *(const ull*)&sw2[ol][kk];
            ull wb = *(const ull*)&sw2[ol + 32][kk];
#pragma unroll
            for (int j = 0; j < 4; j++) {
                ull h2 = *(const ull*)&sh2[bg * 4 + j][kk];
                asm("fma.rn.f32x2 %0, %1, %2, %0;" : "+l"(accA[j]) : "l"(h2), "l"(wa));
                asm("fma.rn.f32x2 %0, %1, %2, %0;" : "+l"(accB[j]) : "l"(h2), "l"(wb));
            }
        }
        __syncthreads();
    }
    int o0 = obase + ol, o1 = obase + 32 + ol;
#pragma unroll
    for (int j = 0; j < 4; j++) {
        float lo, hi;
        int p = bg * 8 + j * 2;
        if (o0 < NOUT) {
            asm("mov.b64 {%0, %1}, %2;" : "=f"(lo), "=f"(hi) : "l"(accA[j]));
            atomicAdd(&out[(size_t)p * NOUT + o0], lo);
            atomicAdd(&out[(size_t)(p + 1) * NOUT + o0], hi);
        }
        if (o1 < NOUT) {
            asm("mov.b64 {%0, %1}, %2;" : "=f"(lo), "=f"(hi) : "l"(accB[j]));
            atomicAdd(&out[(size_t)p * NOUT + o1], lo);
            atomicAdd(&out[(size_t)(p + 1) * NOUT + o1], hi);
        }
    }
}

// ---------------------------------------------------------------------------
// Lazy side-stream / events: created on the FIRST (non-captured) call;
// capture only records record/wait — the standard capturable fork/join.
// ---------------------------------------------------------------------------
static cudaStream_t side_stream() {
    static cudaStream_t s = [] {
        cudaStream_t t;
        cudaStreamCreateWithFlags(&t, cudaStreamNonBlocking);
        return t;
    }();
    return s;
}
static cudaEvent_t fork_event() {
    static cudaEvent_t e = [] {
        cudaEvent_t t;
        cudaEventCreateWithFlags(&t, cudaEventDisableTiming);
        return t;
    }();
    return e;
}
static cudaEvent_t join_event() {
    static cudaEvent_t e = [] {
        cudaEvent_t t;
        cudaEventCreateWithFlags(&t, cudaEventDisableTiming);
        return t;
    }();
    return e;
}

// ---------------------------------------------------------------------------
extern "C" void kernel_launch(void* const* d_in, const int* in_sizes, int n_in,
                              void* d_out, int out_size) {
    const float* enc = (const float*)d_in[0];   // [64,1024]
    const float* mem = (const float*)d_in[1];   // [64,4096,1024]
    const float* W1  = (const float*)d_in[2];   // [4096,2048]
    const float* b1  = (const float*)d_in[3];   // [4096]
    const float* W2  = (const float*)d_in[4];   // [1000,4096]
    const float* b2  = (const float*)d_in[5];   // [1000]
    float* out = (float*)d_out;                 // [64,1000]

    cudaStream_t s2 = side_stream();
    cudaEvent_t evF = fork_event();
    cudaEvent_t evJ = join_event();

    // main stream: full dependency chain
    pre_all<<<1594, 256>>>(enc, b1, b2, out);

    // fork: k4a + L2 warm run concurrently with k1/k2/k3
    cudaEventRecord(evF, 0);
    cudaStreamWaitEvent(s2, evF, 0);
    k4a_fc1<<<dim3(BB, 2), 256, 0, s2>>>(enc, W1);
    l2_warm<<<3048, 256, 0, s2>>>(W1, W2);
    cudaEventRecord(evJ, s2);

    k1_scores<<<(BB * NN) / 64, 256>>>(mem);
    k2_sparsemax<<<BB, 512>>>();
    k3_weighted_sum<<<dim3(BB, 16), 256>>>(mem);
    k4b_fc1<<<dim3(BB, 2), 256>>>(W1);

    // join: k5 needs h1 complete (k4a side + k4b main)
    cudaStreamWaitEvent(0, evJ, 0);
    k5_fc2<<<dim3(16, 8), 256>>>(W2, out);
}

// round 14
// speedup vs baseline: 1.2324x; 1.0162x over previous
#include <cuda_runtime.h>
#include <math.h>

#define BB   64
#define NN   4096
#define DD   1024
#define DIN  2048
#define DHID 4096
#define NOUT 1000

typedef unsigned long long ull;

// ---- scratch (device globals; no allocation allowed) ----
__device__ float g_xn[BB * DD];        // normalized encoder
__device__ float g_z[BB * NN];         // sparsemax input scores
__device__ int   g_nzidx[BB * NN];     // compacted support indices
__device__ float g_nzw[BB * NN];       // compacted weights
__device__ int   g_nnz[BB];
__device__ float g_memvec[BB * DD];    // weighted memory readout (atomic acc)
__device__ float g_h1[BB * DHID];      // hidden pre-activations (bias + atomic acc)
__device__ float g_sink;               // DCE-blocker for the L2 warm kernel

// ---------------------------------------------------------------------------
// PRE: blocks [0,64):     xn = enc / max(||enc||,1e-6)
//      blocks [64,1088):  h1 = b1 (bcast)
//      blocks [1088,1344): memvec = 0
//      blocks [1344,1594): out = b2 (bcast)
// ---------------------------------------------------------------------------
__global__ void pre_all(const float* __restrict__ enc,
                        const float* __restrict__ b1,
                        const float* __restrict__ b2,
                        float* __restrict__ out) {
    int bid = blockIdx.x;
    if (bid < 64) {
        int b = bid;
        __shared__ float red[256];
        float ssq = 0.f;
        for (int i = threadIdx.x; i < DD; i += 256) {
            float v = enc[b * DD + i];
            ssq = fmaf(v, v, ssq);
        }
        red[threadIdx.x] = ssq;
        __syncthreads();
        for (int s = 128; s > 0; s >>= 1) {
            if (threadIdx.x < s) red[threadIdx.x] += red[threadIdx.x + s];
            __syncthreads();
        }
        float inv = 1.f / fmaxf(sqrtf(red[0]), 1e-6f);
        for (int i = threadIdx.x; i < DD; i += 256)
            g_xn[b * DD + i] = enc[b * DD + i] * inv;
    } else if (bid < 1088) {
        int i = (bid - 64) * 256 + threadIdx.x;        // BB*DHID
        g_h1[i] = b1[i & (DHID - 1)];
    } else if (bid < 1344) {
        int i = (bid - 1088) * 256 + threadIdx.x;      // BB*DD
        g_memvec[i] = 0.f;
    } else {
        int i = (bid - 1344) * 256 + threadIdx.x;      // BB*NOUT
        if (i < BB * NOUT) out[i] = b2[i % NOUT];
    }
}

// ---------------------------------------------------------------------------
// K1: the 1.07 GB pass (AT DRAM ROOFLINE, 6.66 TB/s — do not touch).
// ---------------------------------------------------------------------------
__global__ void __launch_bounds__(256) k1_scores(const float* __restrict__ mem) {
    int warp = threadIdx.x >> 5, lane = threadIdx.x & 31;
    int rbase = blockIdx.x * 64 + warp * 8;
    int b = rbase >> 12;

    const float4* x4 = (const float4*)g_xn + (size_t)b * (DD / 4);
    float4 x[8];
#pragma unroll
    for (int i = 0; i < 8; i++) x[i] = x4[lane + i * 32];

    const float4* mrow = (const float4*)mem + (size_t)rbase * (DD / 4);

#pragma unroll
    for (int rr = 0; rr < 8; rr += 2) {
        const float4* A = mrow + rr * (DD / 4);
        const float4* C = A + (DD / 4);
        float4 a[8], c[8];
#pragma unroll
        for (int i = 0; i < 8; i++) {
            a[i] = __ldcs(&A[lane + i * 32]);
            c[i] = __ldcs(&C[lane + i * 32]);
        }
        float d0 = 0.f, s0 = 0.f, d1 = 0.f, s1 = 0.f;
#pragma unroll
        for (int i = 0; i < 8; i++) {
            float4 xv = x[i];
            d0 = fmaf(a[i].x, xv.x, fmaf(a[i].y, xv.y, fmaf(a[i].z, xv.z, fmaf(a[i].w, xv.w, d0))));
            s0 = fmaf(a[i].x, a[i].x, fmaf(a[i].y, a[i].y, fmaf(a[i].z, a[i].z, fmaf(a[i].w, a[i].w, s0))));
            d1 = fmaf(c[i].x, xv.x, fmaf(c[i].y, xv.y, fmaf(c[i].z, xv.z, fmaf(c[i].w, xv.w, d1))));
            s1 = fmaf(c[i].x, c[i].x, fmaf(c[i].y, c[i].y, fmaf(c[i].z, c[i].z, fmaf(c[i].w, c[i].w, s1))));
        }
#pragma unroll
        for (int o = 16; o; o >>= 1) {
            d0 += __shfl_xor_sync(0xFFFFFFFFu, d0, o);
            s0 += __shfl_xor_sync(0xFFFFFFFFu, s0, o);
            d1 += __shfl_xor_sync(0xFFFFFFFFu, d1, o);
            s1 += __shfl_xor_sync(0xFFFFFFFFu, s1, o);
        }
        if (lane == 0) {
            g_z[rbase + rr]     = d0 / fmaxf(sqrtf(s0), 1e-6f) - 1.0f;
            g_z[rbase + rr + 1] = d1 / fmaxf(sqrtf(s1), 1e-6f) - 1.0f;
        }
    }
}

// ---------------------------------------------------------------------------
// K2: sparsemax via Michelot fixed point. Parity-buffered smem partials:
//     ONE barrier per iteration, redundant all-warp final reduce.
// ---------------------------------------------------------------------------
__global__ void k2_sparsemax() {
    int b = blockIdx.x, t = threadIdx.x;
    int lane = t & 31, w = t >> 5;             // 16 warps
    __shared__ float sS[2][16], sK[2][16];
    __shared__ int cnt;

    float loc[8];
#pragma unroll
    for (int i = 0; i < 8; i++) loc[i] = g_z[b * NN + t + i * 512];

    float S = 0.f;
#pragma unroll
    for (int i = 0; i < 8; i++) S += loc[i];
#pragma unroll
    for (int o = 16; o; o >>= 1) S += __shfl_xor_sync(0xFFFFFFFFu, S, o);
    if (lane == 0) sS[0][w] = S;
    __syncthreads();
    float tau;
    {
        float ss = 0.f;
#pragma unroll
        for (int i = 0; i < 16; i++) ss += sS[0][i];
        tau = (ss - 1.f) / (float)NN;
    }

    int par = 1;
    for (int it = 0; it < 48; it++) {
        float s = 0.f, k = 0.f;
#pragma unroll
        for (int i = 0; i < 8; i++) {
            float v = loc[i];
            if (v > tau) { s += v; k += 1.f; }
        }
#pragma unroll
        for (int o = 16; o; o >>= 1) {
            s += __shfl_xor_sync(0xFFFFFFFFu, s, o);
            k += __shfl_xor_sync(0xFFFFFFFFu, k, o);
        }
        if (lane == 0) { sS[par][w] = s; sK[par][w] = k; }
        __syncthreads();
        float ss = 0.f, kk = 0.f;
#pragma unroll
        for (int i = 0; i < 16; i++) { ss += sS[par][i]; kk += sK[par][i]; }
        float tn = (ss - 1.f) / kk;        // identical in all threads
        if (!(tn > tau)) break;            // uniform decision
        tau = tn;
        par ^= 1;
    }

    if (t == 0) cnt = 0;
    __syncthreads();
#pragma unroll
    for (int i = 0; i < 8; i++) {
        float wv = loc[i] - tau;
        if (wv > 0.f) {
            int p = atomicAdd(&cnt, 1);
            g_nzidx[b * NN + p] = t + i * 512;
            g_nzw[b * NN + p] = wv;
        }
    }
    __syncthreads();
    if (t == 0) g_nnz[b] = cnt;
}

// ---------------------------------------------------------------------------
// K3: memvec[b,:] += sum over interleaved support pairs of w * mem[b,idx,:]
//     grid (64, 16): proven-best; pair-unroll (MLP=2), ~30 regs.
// ---------------------------------------------------------------------------
__global__ void __launch_bounds__(256) k3_weighted_sum(const float* __restrict__ mem) {
    int b = blockIdx.x, s = blockIdx.y, t = threadIdx.x;
    int nnz = g_nnz[b];

    const float4* base = (const float4*)mem + (size_t)b * NN * (DD / 4);
    const int*   idxp = &g_nzidx[b * NN];
    const float* wp   = &g_nzw[b * NN];

    float4 acc = make_float4(0.f, 0.f, 0.f, 0.f);
    int i = s * 2;
    bool any = (i < nnz);
    for (; i + 2 <= nnz; i += 32) {
        int   j0 = idxp[i],   j1 = idxp[i + 1];
        float w0 = wp[i],     w1 = wp[i + 1];
        float4 m0 = __ldcs(&base[(size_t)j0 * (DD / 4) + t]);
        float4 m1 = __ldcs(&base[(size_t)j1 * (DD / 4) + t]);
        acc.x = fmaf(w0, m0.x, fmaf(w1, m1.x, acc.x));
        acc.y = fmaf(w0, m0.y, fmaf(w1, m1.y, acc.y));
        acc.z = fmaf(w0, m0.z, fmaf(w1, m1.z, acc.z));
        acc.w = fmaf(w0, m0.w, fmaf(w1, m1.w, acc.w));
    }
    if (i < nnz) {
        int j = idxp[i];
        float wv = wp[i];
        float4 m = __ldcs(&base[(size_t)j * (DD / 4) + t]);
        acc.x = fmaf(wv, m.x, acc.x);
        acc.y = fmaf(wv, m.y, acc.y);
        acc.z = fmaf(wv, m.z, acc.z);
        acc.w = fmaf(wv, m.w, acc.w);
    }
    if (!any) return;
    float* dst = &g_memvec[b * DD + t * 4];
    atomicAdd(dst + 0, acc.x);
    atomicAdd(dst + 1, acc.y);
    atomicAdd(dst + 2, acc.z);
    atomicAdd(dst + 3, acc.w);
}

// ---------------------------------------------------------------------------
// K4a (SIDE STREAM, concurrent with k1/k2/k3):
//     h1 += enc @ W1[:, 0:1024]^T   — depends only on pre_all (h1=b1 init).
// ---------------------------------------------------------------------------
__global__ void k4a_fc1(const float* __restrict__ enc,
                        const float* __restrict__ W1) {
    __shared__ float2 sw2[64][33];
    __shared__ float2 sh2[32][33];
    int t = threadIdx.x;
    int obase = blockIdx.x * 64;
    int koff = blockIdx.y * 512;
    int ol = t & 31;
    int bg = t >> 5;

    ull accA[4] = {0ull, 0ull, 0ull, 0ull};
    ull accB[4] = {0ull, 0ull, 0ull, 0ull};

    for (int kc = koff; kc < koff + 512; kc += 32) {
#pragma unroll
        for (int i = 0; i < 8; i++) {
            int e = t + i * 256;
            int row = e >> 5, col = e & 31;
            ((float*)&sh2[row >> 1][col])[row & 1] = enc[row * DD + kc + col];
        }
#pragma unroll
        for (int i = 0; i < 8; i++) {
            int e = t + i * 256;
            int row = e >> 5, col = e & 31;
            float wv = W1[(size_t)(obase + row) * DIN + kc + col];
            sw2[row][col] = make_float2(wv, wv);
        }
        __syncthreads();
#pragma unroll
        for (int kk = 0; kk < 32; kk++) {
            ull wa = *(const ull*)&sw2[ol][kk];
            ull wb = *(const ull*)&sw2[ol + 32][kk];
#pragma unroll
            for (int j = 0; j < 4; j++) {
                ull h2 = *(const ull*)&sh2[bg * 4 + j][kk];
                asm("fma.rn.f32x2 %0, %1, %2, %0;" : "+l"(accA[j]) : "l"(h2), "l"(wa));
                asm("fma.rn.f32x2 %0, %1, %2, %0;" : "+l"(accB[j]) : "l"(h2), "l"(wb));
            }
        }
        __syncthreads();
    }
    int o0 = obase + ol, o1 = obase + 32 + ol;
#pragma unroll
    for (int j = 0; j < 4; j++) {
        float lo, hi;
        int p = bg * 8 + j * 2;
        asm("mov.b64 {%0, %1}, %2;" : "=f"(lo), "=f"(hi) : "l"(accA[j]));
        atomicAdd(&g_h1[(size_t)p * DHID + o0], lo);
        atomicAdd(&g_h1[(size_t)(p + 1) * DHID + o0], hi);
        asm("mov.b64 {%0, %1}, %2;" : "=f"(lo), "=f"(hi) : "l"(accB[j]));
        atomicAdd(&g_h1[(size_t)p * DHID + o1], lo);
        atomicAdd(&g_h1[(size_t)(p + 1) * DHID + o1], hi);
    }
}

// ---------------------------------------------------------------------------
// WARM (SIDE STREAM, after k4a, still under k1): touch W1[:,1024:2048] and W2
//     via __ldcg so k4b/k5 hit L2 instead of DRAM.
// ---------------------------------------------------------------------------
__global__ void l2_warm(const float* __restrict__ W1,
                        const float* __restrict__ W2) {
    int t = threadIdx.x;
    float acc = 0.f;
    if (blockIdx.x < 2048) {
        int row = blockIdx.x * 2;
#pragma unroll
        for (int r = 0; r < 2; r++) {
            const float4* p = (const float4*)(W1 + (size_t)(row + r) * DIN + DD);
            float4 v = __ldcg(&p[t]);
            acc += v.x + v.y + v.z + v.w;
        }
    } else {
        int row = blockIdx.x - 2048;
        const float4* p = (const float4*)(W2 + (size_t)row * DHID);
#pragma unroll
        for (int r = 0; r < 4; r++) {
            float4 v = __ldcg(&p[t + r * 256]);
            acc += v.x + v.y + v.z + v.w;
        }
    }
    if (acc == 1.23456789e+30f) g_sink = acc;
}

// ---------------------------------------------------------------------------
// K4b half: h1 += memvec @ W1[:, 1024:2048]^T for OUTPUT columns
//     [xoff*64, (xoff+32)*64). grid (32, 2); K-chunk 512.
// ---------------------------------------------------------------------------
__global__ void k4b_fc1(const float* __restrict__ W1, int xoff) {
    __shared__ float2 sw2[64][33];
    __shared__ float2 sh2[32][33];
    int t = threadIdx.x;
    int obase = (blockIdx.x + xoff) * 64;
    int koff = blockIdx.y * 512;
    int ol = t & 31;
    int bg = t >> 5;

    ull accA[4] = {0ull, 0ull, 0ull, 0ull};
    ull accB[4] = {0ull, 0ull, 0ull, 0ull};

    for (int kc = koff; kc < koff + 512; kc += 32) {
#pragma unroll
        for (int i = 0; i < 8; i++) {
            int e = t + i * 256;
            int row = e >> 5, col = e & 31;
            ((float*)&sh2[row >> 1][col])[row & 1] = g_memvec[row * DD + kc + col];
        }
#pragma unroll
        for (int i = 0; i < 8; i++) {
            int e = t + i * 256;
            int row = e >> 5, col = e & 31;
            float wv = W1[(size_t)(obase + row) * DIN + DD + kc + col];
            sw2[row][col] = make_float2(wv, wv);
        }
        __syncthreads();
#pragma unroll
        for (int kk = 0; kk < 32; kk++) {
            ull wa = *(const ull*)&sw2[ol][kk];
            ull wb = *(const ull*)&sw2[ol + 32][kk];
#pragma unroll
            for (int j = 0; j < 4; j++) {
                ull h2 = *(const ull*)&sh2[bg * 4 + j][kk];
                asm("fma.rn.f32x2 %0, %1, %2, %0;" : "+l"(accA[j]) : "l"(h2), "l"(wa));
                asm("fma.rn.f32x2 %0, %1, %2, %0;" : "+l"(accB[j]) : "l"(h2), "l"(wb));
            }
        }
        __syncthreads();
    }
    int o0 = obase + ol, o1 = obase + 32 + ol;
#pragma unroll
    for (int j = 0; j < 4; j++) {
        float lo, hi;
        int p = bg * 8 + j * 2;
        asm("mov.b64 {%0, %1}, %2;" : "=f"(lo), "=f"(hi) : "l"(accA[j]));
        atomicAdd(&g_h1[(size_t)p * DHID + o0], lo);
        atomicAdd(&g_h1[(size_t)(p + 1) * DHID + o0], hi);
        asm("mov.b64 {%0, %1}, %2;" : "=f"(lo), "=f"(hi) : "l"(accB[j]));
        atomicAdd(&g_h1[(size_t)p * DHID + o1], lo);
        atomicAdd(&g_h1[(size_t)(p + 1) * DHID + o1], hi);
    }
}

// ---------------------------------------------------------------------------
// K5 half: out += relu(h1[:, K-range]) @ W2[:, K-range]^T for
//     K-range [yoff*512, (yoff+4)*512). grid (16, 4); relu fused.
//     Depends only on the k4b half covering the same h1 columns (+ k4a).
// ---------------------------------------------------------------------------
__global__ void k5_fc2(const float* __restrict__ W2, float* __restrict__ out,
                       int yoff) {
    __shared__ float2 sw2[64][33];
    __shared__ float2 sh2[32][33];
    int t = threadIdx.x;
    int obase = blockIdx.x * 64;
    int kbeg = (blockIdx.y + yoff) * 512;
    int ol = t & 31;
    int bg = t >> 5;

    ull accA[4] = {0ull, 0ull, 0ull, 0ull};
    ull accB[4] = {0ull, 0ull, 0ull, 0ull};

    for (int kc = kbeg; kc < kbeg + 512; kc += 32) {
#pragma unroll
        for (int i = 0; i < 8; i++) {
            int e = t + i * 256;
            int row = e >> 5, col = e & 31;
            float v = fmaxf(g_h1[(size_t)row * DHID + kc + col], 0.f);  // relu
            ((float*)&sh2[row >> 1][col])[row & 1] = v;
        }
#pragma unroll
        for (int i = 0; i < 8; i++) {
            int e = t + i * 256;
            int row = e >> 5, col = e & 31;
            int o = obase + row;
            float wv = (o < NOUT) ? W2[(size_t)o * DHID + kc + col] : 0.f;
            sw2[row][col] = make_float2(wv, wv);
        }
        __syncthreads();
#pragma unroll
        for (int kk = 0; kk < 32; kk++) {
            ull wa = *(const ull*)&sw2[ol][kk];
            ull wb = *(const ull*)&sw2[ol + 32][kk];
#pragma unroll
            for (int j = 0; j < 4; j++) {
                ull h2 = *(const ull*)&sh2[bg * 4 + j][kk];
                asm("fma.rn.f32x2 %0, %1, %2, %0;" : "+l"(accA[j]) : "l"(h2), "l"(wa));
                asm("fma.rn.f32x2 %0, %1, %2, %0;" : "+l"(accB[j]) : "l"(h2), "l"(wb));
            }
        }
        __syncthreads();
    }
    int o0 = obase + ol, o1 = obase + 32 + ol;
#pragma unroll
    for (int j = 0; j < 4; j++) {
        float lo, hi;
        int p = bg * 8 + j * 2;
        if (o0 < NOUT) {
            asm("mov.b64 {%0, %1}, %2;" : "=f"(lo), "=f"(hi) : "l"(accA[j]));
            atomicAdd(&out[(size_t)p * NOUT + o0], lo);
            atomicAdd(&out[(size_t)(p + 1) * NOUT + o0], hi);
        }
        if (o1 < NOUT) {
            asm("mov.b64 {%0, %1}, %2;" : "=f"(lo), "=f"(hi) : "l"(accB[j]));
            atomicAdd(&out[(size_t)p * NOUT + o1], lo);
            atomicAdd(&out[(size_t)(p + 1) * NOUT + o1], hi);
        }
    }
}

// ---------------------------------------------------------------------------
// Lazy stream/events (the twice-validated 2-stream topology): created on the
// FIRST (non-captured) call; capture only records record/wait.
// ---------------------------------------------------------------------------
static cudaStream_t side_stream() {
    static cudaStream_t s = [] {
        cudaStream_t t;
        cudaStreamCreateWithFlags(&t, cudaStreamNonBlocking);
        return t;
    }();
    return s;
}
static cudaEvent_t lazy_event(int i) {
    static cudaEvent_t e[4] = {};
    if (!e[i]) cudaEventCreateWithFlags(&e[i], cudaEventDisableTiming);
    return e[i];
}

// ---------------------------------------------------------------------------
extern "C" void kernel_launch(void* const* d_in, const int* in_sizes, int n_in,
                              void* d_out, int out_size) {
    const float* enc = (const float*)d_in[0];   // [64,1024]
    const float* mem = (const float*)d_in[1];   // [64,4096,1024]
    const float* W1  = (const float*)d_in[2];   // [4096,2048]
    const float* b1  = (const float*)d_in[3];   // [4096]
    const float* W2  = (const float*)d_in[4];   // [1000,4096]
    const float* b2  = (const float*)d_in[5];   // [1000]
    float* out = (float*)d_out;                 // [64,1000]

    cudaStream_t s2 = side_stream();
    cudaEvent_t evF  = lazy_event(0);           // fork after pre
    cudaEvent_t evK3 = lazy_event(1);           // k3 done (main)
    cudaEvent_t evJ  = lazy_event(2);           // k4a done (side)
    cudaEvent_t evB  = lazy_event(3);           // side branch done

    // main stream: full dependency chain
    pre_all<<<1594, 256>>>(enc, b1, b2, out);

    // fork: side stream runs k4a + L2 warm under k1's window
    cudaEventRecord(evF, 0);
    cudaStreamWaitEvent(s2, evF, 0);
    k4a_fc1<<<dim3(BB, 2), 256, 0, s2>>>(enc, W1);
    cudaEventRecord(evJ, s2);                   // k4a (h1 enc-half) complete
    l2_warm<<<3048, 256, 0, s2>>>(W1, W2);

    k1_scores<<<(BB * NN) / 64, 256>>>(mem);
    k2_sparsemax<<<BB, 512>>>();
    k3_weighted_sum<<<dim3(BB, 16), 256>>>(mem);
    cudaEventRecord(evK3, 0);

    // pipelined k4b->k5 halves over 2048-wide h1-column ranges:
    //   half B on the side stream (already past k4a/warm; wait k3)
    cudaStreamWaitEvent(s2, evK3, 0);
    k4b_fc1<<<dim3(32, 2), 256, 0, s2>>>(W1, 32);   // h1 cols [2048,4096)
    k5_fc2<<<dim3(16, 4), 256, 0, s2>>>(W2, out, 4); // K [2048,4096)
    cudaEventRecord(evB, s2);

    //   half A on the main stream (needs k4a done: k5-A reads its columns)
    cudaStreamWaitEvent(0, evJ, 0);
    k4b_fc1<<<dim3(32, 2), 256>>>(W1, 0);            // h1 cols [0,2048)
    k5_fc2<<<dim3(16, 4), 256>>>(W2, out, 0);        // K [0,2048)

    // join side branch back into the captured (main) stream
    cudaStreamWaitEvent(0, evB, 0);
}